// round 12
// baseline (speedup 1.0000x reference)
#include <cuda_runtime.h>

// KAConvComparision: rational (Pade) per-tap conv.
// x: (4,16,64,64) f32   nums: (32,16,3,3,6) f32   denoms: (32,16,3,3,4) f32
// out: (4,32,64,64) f32
// out[b,f,y,x] = sum_{c,k} P_{f,c,k}(v) / (1 + |Qs_{f,c,k}(v)|)
//
// R9: R5 geometry (tile 32x8, 1024 blocks, 128 thr, single-pass staging,
// 6 blocks/SM) + depth-1 software pipeline of the coefficient LDS stream
// (rolling pointer over the 144 linear tap records; prefetch the Horner-head
// q0..q2 one tap ahead) + packed-abs denominator (LOP3 on alu pipe + add2)
// + packed filter-pair accumulate. 11 fma-pipe ops / packed eval-pair.

#define CC 16
#define HH 64
#define WW 64
#define FF 32
#define TS_X 32
#define TS_Y 8
#define XR   10          // tile rows + halo
#define XW   34          // tile cols + halo (even -> float2 aligned)

typedef unsigned long long u64;

#define ABS2_MASK 0x7FFFFFFF7FFFFFFFull
#define ONE2      0x3F8000003F800000ull   // packed {1.0f, 1.0f}

__device__ __forceinline__ u64 pk2(float lo, float hi) {
    u64 r; asm("mov.b64 %0, {%1, %2};" : "=l"(r) : "f"(lo), "f"(hi)); return r;
}
__device__ __forceinline__ void upk2(u64 v, float& lo, float& hi) {
    asm("mov.b64 {%0, %1}, %2;" : "=f"(lo), "=f"(hi) : "l"(v));
}
__device__ __forceinline__ u64 fma2(u64 a, u64 b, u64 c) {
    u64 d; asm("fma.rn.f32x2 %0, %1, %2, %3;" : "=l"(d) : "l"(a), "l"(b), "l"(c)); return d;
}
__device__ __forceinline__ u64 mul2(u64 a, u64 b) {
    u64 d; asm("mul.rn.f32x2 %0, %1, %2;" : "=l"(d) : "l"(a), "l"(b)); return d;
}
__device__ __forceinline__ u64 add2(u64 a, u64 b) {
    u64 d; asm("add.rn.f32x2 %0, %1, %2;" : "=l"(d) : "l"(a), "l"(b)); return d;
}
__device__ __forceinline__ float rcpf(float a) {
    float r; asm("rcp.approx.f32 %0, %1;" : "=f"(r) : "f"(a)); return r;
}

__global__ __launch_bounds__(128, 6)
void kaconv_kernel(const float* __restrict__ x,
                   const float* __restrict__ nums,
                   const float* __restrict__ denoms,
                   float* __restrict__ out)
{
    // x tile: 16 ch x 10 rows x 34 cols.  21.76 KB
    __shared__ float xs[CC * XR * XW];
    // coeffs for ONE filter pair, 144 linear tap records of 5 ulonglong2
    // (+1 pad record so the rolling prefetch never reads out of bounds).
    __shared__ __align__(16) float cf[(CC * 9 + 1) * 20];

    const int tid  = threadIdx.x;
    const int tcol = blockIdx.x & 1;      // 2 col tiles
    const int trow = blockIdx.x >> 1;     // 8 row tiles
    const int fp   = blockIdx.y;          // 16 filter pairs
    const int b    = blockIdx.z;

    const int x0 = tcol * TS_X - 1;
    const int y0 = trow * TS_Y - 1;

    // ---- stage x tile (zero-padded halo) ----
    for (int i = tid; i < CC * XR * XW; i += 128) {
        int c   = i / (XR * XW);
        int rem = i - c * (XR * XW);
        int r   = rem / XW;
        int col = rem - r * XW;
        int gy = y0 + r, gx = x0 + col;
        float v = 0.0f;
        if ((unsigned)gy < (unsigned)HH && (unsigned)gx < (unsigned)WW)
            v = x[((b * CC + c) * HH + gy) * WW + gx];
        xs[i] = v;
    }

    // ---- stage packed coefficient pairs ----
    for (int i = tid; i < CC * 9 * 20; i += 128) {
        int h  = i & 1;            // filter within pair
        int t  = i >> 1;
        int j  = t % 10;           // 0..5 = a0..a5, 6..9 = b1..b4
        int ck = t / 10;           // c*9 + k
        int f  = fp * 2 + h;
        float v;
        if (j < 6) v = nums[(f * CC * 9 + ck) * 6 + j];
        else       v = denoms[(f * CC * 9 + ck) * 4 + (j - 6)];
        cf[i] = v;
    }
    __syncthreads();

    const int tx = tid & 15;    // 16 col groups of 2 px
    const int ty = tid >> 4;    // 8 rows

    u64 acc0 = 0ull, acc1 = 0ull;   // packed (f0,f1) accumulators per pixel

    const float* xb = &xs[ty * XW + tx * 2];

    // rolling coefficient pointer over 144 linear tap records
    const ulonglong2* cp = (const ulonglong2*)cf;
    // prefetch Horner head of tap 0
    ulonglong2 n0 = cp[0], n1 = cp[1], n2 = cp[2];

    #pragma unroll 1
    for (int c = 0; c < CC; c++) {
        const float* xc = xb + c * (XR * XW);
        #pragma unroll
        for (int ky = 0; ky < 3; ky++) {
            // 4 consecutive cols: cover kx 0..2 x px 0..1
            float2 A = *(const float2*)(xc + ky * XW);
            float2 Bv = *(const float2*)(xc + ky * XW + 2);
            u64 wv[4];
            wv[0] = pk2(A.x,  A.x);
            wv[1] = pk2(A.y,  A.y);
            wv[2] = pk2(Bv.x, Bv.x);
            wv[3] = pk2(Bv.y, Bv.y);
            #pragma unroll
            for (int kx = 0; kx < 3; kx++) {
                ulonglong2 q0 = n0, q1 = n1, q2 = n2;   // head (prefetched)
                ulonglong2 q3 = cp[3];                  // {b1,b2} JIT
                ulonglong2 q4 = cp[4];                  // {b3,b4} JIT
                cp += 5;
                n0 = cp[0]; n1 = cp[1]; n2 = cp[2];     // prefetch next tap
                // pixel 0
                {
                    u64 w = wv[kx];
                    u64 P = fma2(q2.y, w, q2.x);
                    P = fma2(P, w, q1.y);
                    P = fma2(P, w, q1.x);
                    P = fma2(P, w, q0.y);
                    P = fma2(P, w, q0.x);
                    u64 T = fma2(q4.y, w, q4.x);
                    T = fma2(T, w, q3.y);
                    T = fma2(T, w, q3.x);
                    u64 Qs = mul2(T, w);
                    u64 Q2 = add2(Qs & ABS2_MASK, ONE2);   // 1 + |Qs| packed
                    float ql, qh;
                    upk2(Q2, ql, qh);
                    float r0 = rcpf(ql);
                    float r1 = rcpf(qh);
                    acc0 = fma2(P, pk2(r0, r1), acc0);
                }
                // pixel 1
                {
                    u64 w = wv[kx + 1];
                    u64 P = fma2(q2.y, w, q2.x);
                    P = fma2(P, w, q1.y);
                    P = fma2(P, w, q1.x);
                    P = fma2(P, w, q0.y);
                    P = fma2(P, w, q0.x);
                    u64 T = fma2(q4.y, w, q4.x);
                    T = fma2(T, w, q3.y);
                    T = fma2(T, w, q3.x);
                    u64 Qs = mul2(T, w);
                    u64 Q2 = add2(Qs & ABS2_MASK, ONE2);
                    float ql, qh;
                    upk2(Q2, ql, qh);
                    float r0 = rcpf(ql);
                    float r1 = rcpf(qh);
                    acc1 = fma2(P, pk2(r0, r1), acc1);
                }
            }
        }
    }

    // ---- unpack & write out (float2 per filter, gxb even) ----
    float o00, o10, o01, o11;
    upk2(acc0, o00, o10);
    upk2(acc1, o01, o11);

    const int gy  = trow * TS_Y + ty;
    const int gxb = tcol * TS_X + tx * 2;
    const int f0  = fp * 2;
    *(float2*)&out[((b * FF + f0    ) * HH + gy) * WW + gxb] = make_float2(o00, o01);
    *(float2*)&out[((b * FF + f0 + 1) * HH + gy) * WW + gxb] = make_float2(o10, o11);
}

extern "C" void kernel_launch(void* const* d_in, const int* in_sizes, int n_in,
                              void* d_out, int out_size)
{
    const float* x      = (const float*)d_in[0];
    const float* nums   = (const float*)d_in[1];
    const float* denoms = (const float*)d_in[2];
    float* out          = (float*)d_out;

    dim3 grid(16, FF / 2, 4);   // (2 col x 8 row tiles, 16 filter pairs, batch)
    kaconv_kernel<<<grid, 128>>>(x, nums, denoms, out);
}

// round 16
// speedup vs baseline: 1.0098x; 1.0098x over previous
#include <cuda_runtime.h>

// KAConvComparision: rational (Pade) per-tap conv.
// x: (4,16,64,64) f32   nums: (32,16,3,3,6) f32   denoms: (32,16,3,3,4) f32
// out: (4,32,64,64) f32
// out[b,f,y,x] = sum_{c,k} P_{f,c,k}(v) / (1 + |Qs_{f,c,k}(v)|)
//
// R12 = R5 (best, 51.7us) with ONE delta: c-loop unroll 1 -> 2 so ptxas can
// software-pipeline across taps (overlap next tap's coeff LDS + Horner heads
// with current tap's MUFU->acc tails). launch_bounds(128,6) caps regs at 85
// so 6 blocks/SM is preserved. No manual prefetch, no packed abs (both
// regressed via alu-pipe inflation in R7/R9).

#define CC 16
#define HH 64
#define WW 64
#define FF 32
#define TS_X 32
#define TS_Y 8
#define XR   10          // tile rows + halo
#define XW   34          // tile cols + halo (even -> float2 aligned)

typedef unsigned long long u64;

__device__ __forceinline__ u64 pk2(float lo, float hi) {
    u64 r; asm("mov.b64 %0, {%1, %2};" : "=l"(r) : "f"(lo), "f"(hi)); return r;
}
__device__ __forceinline__ void upk2(u64 v, float& lo, float& hi) {
    asm("mov.b64 {%0, %1}, %2;" : "=f"(lo), "=f"(hi) : "l"(v));
}
__device__ __forceinline__ u64 fma2(u64 a, u64 b, u64 c) {
    u64 d; asm("fma.rn.f32x2 %0, %1, %2, %3;" : "=l"(d) : "l"(a), "l"(b), "l"(c)); return d;
}
__device__ __forceinline__ u64 mul2(u64 a, u64 b) {
    u64 d; asm("mul.rn.f32x2 %0, %1, %2;" : "=l"(d) : "l"(a), "l"(b)); return d;
}
__device__ __forceinline__ float rcpf(float a) {
    float r; asm("rcp.approx.f32 %0, %1;" : "=f"(r) : "f"(a)); return r;
}

__global__ __launch_bounds__(128, 6)
void kaconv_kernel(const float* __restrict__ x,
                   const float* __restrict__ nums,
                   const float* __restrict__ denoms,
                   float* __restrict__ out)
{
    // x tile: 16 ch x 10 rows x 34 cols, stride 34 (even: float2-aligned).
    __shared__ float xs[CC * XR * XW];                    // 21.76 KB
    // coeffs for ONE filter pair: cf[(ck*10 + j)*2 + h], 80B per (c,k) record.
    __shared__ __align__(16) float cf[CC * 9 * 10 * 2];   // 11.52 KB

    const int tid  = threadIdx.x;
    const int tcol = blockIdx.x & 1;      // 2 col tiles
    const int trow = blockIdx.x >> 1;     // 8 row tiles
    const int fp   = blockIdx.y;          // 16 filter pairs
    const int b    = blockIdx.z;

    const int x0 = tcol * TS_X - 1;
    const int y0 = trow * TS_Y - 1;

    // ---- stage x tile (zero-padded halo) ----
    for (int i = tid; i < CC * XR * XW; i += 128) {
        int c   = i / (XR * XW);
        int rem = i - c * (XR * XW);
        int r   = rem / XW;
        int col = rem - r * XW;
        int gy = y0 + r, gx = x0 + col;
        float v = 0.0f;
        if ((unsigned)gy < (unsigned)HH && (unsigned)gx < (unsigned)WW)
            v = x[((b * CC + c) * HH + gy) * WW + gx];
        xs[i] = v;
    }

    // ---- stage packed coefficient pairs for this filter pair ----
    for (int i = tid; i < CC * 9 * 20; i += 128) {
        int h  = i & 1;            // filter within pair
        int t  = i >> 1;
        int j  = t % 10;           // 0..5 = a0..a5, 6..9 = b1..b4
        int ck = t / 10;           // c*9 + k
        int f  = fp * 2 + h;
        float v;
        if (j < 6) v = nums[(f * CC * 9 + ck) * 6 + j];
        else       v = denoms[(f * CC * 9 + ck) * 4 + (j - 6)];
        cf[i] = v;
    }
    __syncthreads();

    const int tx = tid & 15;    // 16 col groups of 2 px
    const int ty = tid >> 4;    // 8 rows

    float acc00 = 0.0f, acc01 = 0.0f, acc10 = 0.0f, acc11 = 0.0f;

    // per-thread fixed bases: inner offsets become compile-time immediates
    const float* xb = &xs[ty * XW + tx * 2];
    const ulonglong2* cb = (const ulonglong2*)cf;

    #pragma unroll 2
    for (int c = 0; c < CC; c++) {
        const float* xc = xb + c * (XR * XW);
        const ulonglong2* cc_ = cb + c * (9 * 20 / 4);   // 9 records x 5 u2
        #pragma unroll
        for (int ky = 0; ky < 3; ky++) {
            // 4 consecutive cols for this row: covers kx 0..2, p 0..1
            float2 A  = *(const float2*)(xc + ky * XW);
            float2 Bv = *(const float2*)(xc + ky * XW + 2);
            u64 wv[4];
            wv[0] = pk2(A.x,  A.x);
            wv[1] = pk2(A.y,  A.y);
            wv[2] = pk2(Bv.x, Bv.x);
            wv[3] = pk2(Bv.y, Bv.y);
            #pragma unroll
            for (int kx = 0; kx < 3; kx++) {
                const ulonglong2* cp = cc_ + (ky * 3 + kx) * 5;
                ulonglong2 q0 = cp[0];  // {a0,a1} packed pairs
                ulonglong2 q1 = cp[1];  // {a2,a3}
                ulonglong2 q2 = cp[2];  // {a4,a5}
                ulonglong2 q3 = cp[3];  // {b1,b2}
                ulonglong2 q4 = cp[4];  // {b3,b4}
                // pixel 0
                {
                    u64 w = wv[kx];
                    u64 P = fma2(q2.y, w, q2.x);
                    P = fma2(P, w, q1.y);
                    P = fma2(P, w, q1.x);
                    P = fma2(P, w, q0.y);
                    P = fma2(P, w, q0.x);
                    u64 T = fma2(q4.y, w, q4.x);
                    T = fma2(T, w, q3.y);
                    T = fma2(T, w, q3.x);
                    u64 Qs = mul2(T, w);
                    float ql, qh, pl, ph;
                    upk2(Qs, ql, qh);
                    upk2(P, pl, ph);
                    float r0 = rcpf(1.0f + fabsf(ql));
                    float r1 = rcpf(1.0f + fabsf(qh));
                    acc00 = fmaf(pl, r0, acc00);
                    acc10 = fmaf(ph, r1, acc10);
                }
                // pixel 1
                {
                    u64 w = wv[kx + 1];
                    u64 P = fma2(q2.y, w, q2.x);
                    P = fma2(P, w, q1.y);
                    P = fma2(P, w, q1.x);
                    P = fma2(P, w, q0.y);
                    P = fma2(P, w, q0.x);
                    u64 T = fma2(q4.y, w, q4.x);
                    T = fma2(T, w, q3.y);
                    T = fma2(T, w, q3.x);
                    u64 Qs = mul2(T, w);
                    float ql, qh, pl, ph;
                    upk2(Qs, ql, qh);
                    upk2(P, pl, ph);
                    float r0 = rcpf(1.0f + fabsf(ql));
                    float r1 = rcpf(1.0f + fabsf(qh));
                    acc01 = fmaf(pl, r0, acc01);
                    acc11 = fmaf(ph, r1, acc11);
                }
            }
        }
    }

    // ---- write out (float2, gxb even) ----
    const int gy  = trow * TS_Y + ty;
    const int gxb = tcol * TS_X + tx * 2;
    const int f0  = fp * 2;
    *(float2*)&out[((b * FF + f0    ) * HH + gy) * WW + gxb] = make_float2(acc00, acc01);
    *(float2*)&out[((b * FF + f0 + 1) * HH + gy) * WW + gxb] = make_float2(acc10, acc11);
}

extern "C" void kernel_launch(void* const* d_in, const int* in_sizes, int n_in,
                              void* d_out, int out_size)
{
    const float* x      = (const float*)d_in[0];
    const float* nums   = (const float*)d_in[1];
    const float* denoms = (const float*)d_in[2];
    float* out          = (float*)d_out;

    dim3 grid(16, FF / 2, 4);   // (2 col x 8 row tiles, 16 filter pairs, batch)
    kaconv_kernel<<<grid, 128>>>(x, nums, denoms, out);
}